// round 4
// baseline (speedup 1.0000x reference)
#include <cuda_runtime.h>

typedef unsigned long long u64;

#define LAT   16
#define HID   50
#define HIDP  52          // hidden padded to multiple of 4
#define NQ    (HIDP/4)    // 13
#define TSMAX 132

// ---- packed f32x2 helpers (sm_100+; ptxas never auto-fuses, PTX-only) ----
static __device__ __forceinline__ u64 pk(float lo, float hi){
    u64 r; asm("mov.b64 %0, {%1,%2};" : "=l"(r) : "f"(lo), "f"(hi)); return r;
}
static __device__ __forceinline__ void upk(u64 v, float& lo, float& hi){
    asm("mov.b64 {%0,%1}, %2;" : "=f"(lo), "=f"(hi) : "l"(v));
}
static __device__ __forceinline__ u64 dup2(float x){ return pk(x, x); }
static __device__ __forceinline__ u64 fma2(u64 a, u64 b, u64 c){
    u64 d; asm("fma.rn.f32x2 %0, %1, %2, %3;" : "=l"(d) : "l"(a), "l"(b), "l"(c)); return d;
}
static __device__ __forceinline__ u64 add2(u64 a, u64 b){
    u64 d; asm("add.rn.f32x2 %0, %1, %2;" : "=l"(d) : "l"(a), "l"(b)); return d;
}
static __device__ __forceinline__ float hsum(u64 v){
    float lo, hi; upk(v, lo, hi); return lo + hi;
}

// tanh(x) = 1 - 2/(exp(2x)+1); ex2.approx + rcp.approx -> ~1e-7 rel err
static __device__ __forceinline__ float tanh_fast(float x){
    float e, r;
    float y = x * 2.88539008177792681472f;   // 2*log2(e)
    asm("ex2.approx.f32 %0, %1;" : "=f"(e) : "f"(y));
    float d = e + 1.0f;
    asm("rcp.approx.f32 %0, %1;" : "=f"(r) : "f"(d));
    return fmaf(-2.0f, r, 1.0f);
}

// o = tanh(z @ W1 + b1) @ W2 + b2
// zp[8]  : state packed over latent dim (pairs along the reduction axis)
// sW1t   : [HIDP][LAT]  (transposed: latent-contiguous rows)
// sW2    : [HIDP][LAT]  (output-contiguous rows)
// o[8]   : 16 outputs as f32x2 pairs
static __device__ __forceinline__ void ode_f(const u64* __restrict__ zp,
                                             u64* __restrict__ o,
                                             const float* __restrict__ sW1t,
                                             const float* __restrict__ sb1,
                                             const float* __restrict__ sW2,
                                             const float* __restrict__ sb2)
{
    #pragma unroll
    for (int p = 0; p < 8; ++p) o[p] = *(const u64*)(sb2 + 2*p);

    #pragma unroll 1
    for (int lq = 0; lq < NQ; ++lq){
        const int l = lq * 4;
        u64 p0 = 0, p1 = 0, p2 = 0, p3 = 0;   // (0.f,0.f) bit pattern
        const float* r = sW1t + l*LAT;
        #pragma unroll
        for (int q = 0; q < 4; ++q){
            const ulonglong2 w0 = *(const ulonglong2*)(r           + 4*q);
            const ulonglong2 w1 = *(const ulonglong2*)(r +   LAT   + 4*q);
            const ulonglong2 w2 = *(const ulonglong2*)(r + 2*LAT   + 4*q);
            const ulonglong2 w3 = *(const ulonglong2*)(r + 3*LAT   + 4*q);
            p0 = fma2(zp[2*q], w0.x, p0); p0 = fma2(zp[2*q+1], w0.y, p0);
            p1 = fma2(zp[2*q], w1.x, p1); p1 = fma2(zp[2*q+1], w1.y, p1);
            p2 = fma2(zp[2*q], w2.x, p2); p2 = fma2(zp[2*q+1], w2.y, p2);
            p3 = fma2(zp[2*q], w3.x, p3); p3 = fma2(zp[2*q+1], w3.y, p3);
        }
        const float4 b = *(const float4*)(sb1 + l);
        float hh[4];
        hh[0] = tanh_fast(hsum(p0) + b.x);
        hh[1] = tanh_fast(hsum(p1) + b.y);
        hh[2] = tanh_fast(hsum(p2) + b.z);
        hh[3] = tanh_fast(hsum(p3) + b.w);
        #pragma unroll
        for (int r4 = 0; r4 < 4; ++r4){
            const u64 hd = dup2(hh[r4]);
            const float* wr = sW2 + (l + r4)*LAT;
            #pragma unroll
            for (int q = 0; q < 4; ++q){
                const ulonglong2 w = *(const ulonglong2*)(wr + 4*q);
                o[2*q]     = fma2(hd, w.x, o[2*q]);
                o[2*q + 1] = fma2(hd, w.y, o[2*q + 1]);
            }
        }
    }
}

// y = relu(z @ Wd1 + bd1) @ Wd2 + bd2  (scalar output)
static __device__ __forceinline__ float dec_f(const u64* __restrict__ zp,
                                              const float* __restrict__ sW1t,
                                              const float* __restrict__ sb1,
                                              const float* __restrict__ sw2,
                                              float b2)
{
    float y = b2;
    #pragma unroll 1
    for (int lq = 0; lq < NQ; ++lq){
        const int l = lq * 4;
        u64 p0 = 0, p1 = 0, p2 = 0, p3 = 0;
        const float* r = sW1t + l*LAT;
        #pragma unroll
        for (int q = 0; q < 4; ++q){
            const ulonglong2 w0 = *(const ulonglong2*)(r           + 4*q);
            const ulonglong2 w1 = *(const ulonglong2*)(r +   LAT   + 4*q);
            const ulonglong2 w2 = *(const ulonglong2*)(r + 2*LAT   + 4*q);
            const ulonglong2 w3 = *(const ulonglong2*)(r + 3*LAT   + 4*q);
            p0 = fma2(zp[2*q], w0.x, p0); p0 = fma2(zp[2*q+1], w0.y, p0);
            p1 = fma2(zp[2*q], w1.x, p1); p1 = fma2(zp[2*q+1], w1.y, p1);
            p2 = fma2(zp[2*q], w2.x, p2); p2 = fma2(zp[2*q+1], w2.y, p2);
            p3 = fma2(zp[2*q], w3.x, p3); p3 = fma2(zp[2*q+1], w3.y, p3);
        }
        const float4 b  = *(const float4*)(sb1 + l);
        const float4 w2 = *(const float4*)(sw2 + l);
        y = fmaf(fmaxf(hsum(p0) + b.x, 0.f), w2.x, y);
        y = fmaf(fmaxf(hsum(p1) + b.y, 0.f), w2.y, y);
        y = fmaf(fmaxf(hsum(p2) + b.z, 0.f), w2.z, y);
        y = fmaf(fmaxf(hsum(p3) + b.w, 0.f), w2.w, y);
    }
    return y;
}

__global__ void __launch_bounds__(64, 6) node_kernel(
    const float* __restrict__ x0,  const float* __restrict__ ts,
    const float* __restrict__ We1, const float* __restrict__ be1,
    const float* __restrict__ We2, const float* __restrict__ be2,
    const float* __restrict__ Wo1, const float* __restrict__ bo1,
    const float* __restrict__ Wo2, const float* __restrict__ bo2,
    const float* __restrict__ Wd1, const float* __restrict__ bd1,
    const float* __restrict__ Wd2, const float* __restrict__ bd2,
    float* __restrict__ out, int B, int T)
{
    __shared__ __align__(16) float sWo1t[HIDP*LAT];  // transposed [l][i]
    __shared__ __align__(16) float sWo2 [HIDP*LAT];  // [l][j]
    __shared__ __align__(16) float sWd1t[HIDP*LAT];  // transposed [l][i]
    __shared__ __align__(16) float sWe2 [HIDP*LAT];  // [l][j]
    __shared__ __align__(16) float sWe1 [2*HIDP];
    __shared__ __align__(16) float sbo1 [HIDP];
    __shared__ __align__(16) float sbd1 [HIDP];
    __shared__ __align__(16) float sbe1 [HIDP];
    __shared__ __align__(16) float sWd2 [HIDP];
    __shared__ __align__(16) float sbo2 [LAT];
    __shared__ __align__(16) float sbe2 [LAT];
    __shared__ float sT[TSMAX];

    const int tid = threadIdx.x, bs = blockDim.x;

    for (int idx = tid; idx < HIDP*LAT; idx += bs){
        const int l = idx / LAT, i = idx - l*LAT;     // i = latent (W1t) or out (W2)
        const bool v = (l < HID);
        sWo1t[idx] = v ? Wo1[i*HID + l] : 0.f;        // transpose
        sWd1t[idx] = v ? Wd1[i*HID + l] : 0.f;        // transpose
        sWo2 [idx] = v ? Wo2[l*LAT + i] : 0.f;
        sWe2 [idx] = v ? We2[l*LAT + i] : 0.f;
    }
    for (int idx = tid; idx < HIDP; idx += bs){
        const bool v = (idx < HID);
        sbo1[idx] = v ? bo1[idx] : 0.f;
        sbd1[idx] = v ? bd1[idx] : 0.f;
        sbe1[idx] = v ? be1[idx] : 0.f;
        sWd2[idx] = v ? Wd2[idx] : 0.f;
        sWe1[idx]        = v ? We1[idx]       : 0.f;  // row 0 of (2,HID)
        sWe1[HIDP + idx] = v ? We1[HID + idx] : 0.f;  // row 1
    }
    if (tid < LAT){ sbo2[tid] = bo2[tid]; sbe2[tid] = be2[tid]; }
    const int tcap = (T < TSMAX) ? T : TSMAX;
    for (int idx = tid; idx < tcap; idx += bs) sT[idx] = ts[idx];
    __syncthreads();

    const int b = blockIdx.x * bs + tid;
    if (b >= B) return;

    // ---- encoder: z0 = relu(x0 @ We1 + be1) @ We2 + be2 (packed over latent) ----
    const float2 xv = *(const float2*)(x0 + 2*b);
    u64 z[8];
    #pragma unroll
    for (int p = 0; p < 8; ++p) z[p] = *(const u64*)(sbe2 + 2*p);
    #pragma unroll 1
    for (int l = 0; l < HID; ++l){
        const float h = fmaxf(fmaf(xv.x, sWe1[l], fmaf(xv.y, sWe1[HIDP + l], sbe1[l])), 0.f);
        const u64 hd = dup2(h);
        const float* wr = sWe2 + l*LAT;
        #pragma unroll
        for (int q = 0; q < 4; ++q){
            const ulonglong2 w2 = *(const ulonglong2*)(wr + 4*q);
            z[2*q]     = fma2(hd, w2.x, z[2*q]);
            z[2*q + 1] = fma2(hd, w2.y, z[2*q + 1]);
        }
    }

    u64 zs[8], kk[8], ksum[8];
    const float bd2v = bd2[0];
    float* outp = out + b;
    const u64 two = dup2(2.0f);

    #pragma unroll 1
    for (int t = 0; t < T; ++t){
        outp[(size_t)t * B] = dec_f(z, sWd1t, sbd1, sWd2, bd2v);
        if (t == T - 1) break;

        const float dt = (t + 1 < tcap) ? (sT[t+1] - sT[t]) : (ts[t+1] - ts[t]);
        const u64 hdt = dup2(0.5f * dt);
        const u64 fdt = dup2(dt);
        const u64 sdt = dup2(dt * (1.0f/6.0f));

        ode_f(z, kk, sWo1t, sbo1, sWo2, sbo2);                 // k1
        #pragma unroll
        for (int p = 0; p < 8; ++p){ ksum[p] = kk[p]; zs[p] = fma2(hdt, kk[p], z[p]); }
        ode_f(zs, kk, sWo1t, sbo1, sWo2, sbo2);                // k2
        #pragma unroll
        for (int p = 0; p < 8; ++p){ ksum[p] = fma2(two, kk[p], ksum[p]); zs[p] = fma2(hdt, kk[p], z[p]); }
        ode_f(zs, kk, sWo1t, sbo1, sWo2, sbo2);                // k3
        #pragma unroll
        for (int p = 0; p < 8; ++p){ ksum[p] = fma2(two, kk[p], ksum[p]); zs[p] = fma2(fdt, kk[p], z[p]); }
        ode_f(zs, kk, sWo1t, sbo1, sWo2, sbo2);                // k4
        #pragma unroll
        for (int p = 0; p < 8; ++p){ ksum[p] = add2(ksum[p], kk[p]); z[p] = fma2(sdt, ksum[p], z[p]); }
    }
}

extern "C" void kernel_launch(void* const* d_in, const int* in_sizes, int n_in,
                              void* d_out, int out_size)
{
    const float* x0  = (const float*)d_in[0];
    const float* ts  = (const float*)d_in[1];
    const float* We1 = (const float*)d_in[2];
    const float* be1 = (const float*)d_in[3];
    const float* We2 = (const float*)d_in[4];
    const float* be2 = (const float*)d_in[5];
    const float* Wo1 = (const float*)d_in[6];
    const float* bo1 = (const float*)d_in[7];
    const float* Wo2 = (const float*)d_in[8];
    const float* bo2 = (const float*)d_in[9];
    const float* Wd1 = (const float*)d_in[10];
    const float* bd1 = (const float*)d_in[11];
    const float* Wd2 = (const float*)d_in[12];
    const float* bd2 = (const float*)d_in[13];

    const int B = in_sizes[0] / 2;   // (B, 2)
    const int T = in_sizes[1];       // (T,)
    const int bs = 64;
    const int grid = (B + bs - 1) / bs;

    node_kernel<<<grid, bs>>>(x0, ts, We1, be1, We2, be2, Wo1, bo1,
                              Wo2, bo2, Wd1, bd1, Wd2, bd2,
                              (float*)d_out, B, T);
}